// round 1
// baseline (speedup 1.0000x reference)
#include <cuda_runtime.h>
#include <cstdint>

// Problem constants (fixed by the dataset)
#define DD 480
#define HH 360
#define WWD 32
#define BB 2
#define NPTS_MAX 200000
#define NEG_SLOPE 0.01f
#define BN_EPS 1e-5f

static constexpr int GRID_SZ = BB * DD * HH * WWD;  // 11,059,200

// Scratch (device globals: allowed; zero-initialized at module load)
__device__ int   g_grid[GRID_SZ];          // stores idx+1; 0 == empty
__device__ int   g_nbr133[9 * NPTS_MAX];   // k-major: [k*n + i]
__device__ int   g_nbr313[9 * NPTS_MAX];
__device__ float g_buf1[NPTS_MAX * 32];
__device__ float g_buf2[NPTS_MAX * 32];

// ---------------------------------------------------------------------------
// Kernel 1: scatter point index into dense grid (idx+1; empty cells stay 0
// from static zero-init; same positions rewritten every call -> deterministic)
// ---------------------------------------------------------------------------
__global__ void scatter_grid_kernel(const int* __restrict__ coords, int n) {
    int i = blockIdx.x * blockDim.x + threadIdx.x;
    if (i >= n) return;
    int b = coords[i * 4 + 0];
    int z = coords[i * 4 + 1];
    int y = coords[i * 4 + 2];
    int x = coords[i * 4 + 3];
    int lin = ((b * DD + z) * HH + y) * WWD + x;
    g_grid[lin] = i + 1;
}

// ---------------------------------------------------------------------------
// Kernel 2: build both neighbor tables (OFF_133: dz=0; OFF_313: dy=0)
// k = (d0+1)*3 + (d1+1), d0 = dy (133) / dz (313), d1 = dx
// ---------------------------------------------------------------------------
__global__ void build_nbrs_kernel(const int* __restrict__ coords, int n,
                                  int* __restrict__ nbr133,
                                  int* __restrict__ nbr313) {
    int i = blockIdx.x * blockDim.x + threadIdx.x;
    if (i >= n) return;
    int b = coords[i * 4 + 0];
    int z = coords[i * 4 + 1];
    int y = coords[i * 4 + 2];
    int x = coords[i * 4 + 3];
    int base_bz = (b * DD + z);
#pragma unroll
    for (int k = 0; k < 9; ++k) {
        int d0 = k / 3 - 1;
        int d1 = k % 3 - 1;
        // OFF_133: (0, dy, dx)
        {
            int ny = y + d0, nx = x + d1;
            int r = -1;
            if (ny >= 0 && ny < HH && nx >= 0 && nx < WWD)
                r = g_grid[(base_bz * HH + ny) * WWD + nx] - 1;
            nbr133[k * n + i] = r;
        }
        // OFF_313: (dz, 0, dx)
        {
            int nz = z + d0, nx = x + d1;
            int r = -1;
            if (nz >= 0 && nz < DD && nx >= 0 && nx < WWD)
                r = g_grid[((b * DD + nz) * HH + y) * WWD + nx] - 1;
            nbr313[k * n + i] = r;
        }
    }
}

// ---------------------------------------------------------------------------
// Kernel 3: fused gather-GEMM + BN + LeakyReLU (+ optional residual add)
//
//   out[i,c] = lrelu( (sum_k sum_ci in[nbr[k,i], ci] * W[k,ci,c]) * scale[c]
//                     + shift[c] )            [+ res[i,c] if ADD]
//
// Tile: 64 points x 32 channels per block, 128 threads.
// Thread computes 4 points x 4 channels using packed fma.rn.f32x2.
// smem: full W (9*CIN*32 floats) + one k-slice of gathered A (CIN x 64).
// ---------------------------------------------------------------------------
template <int CIN, bool ADD>
__global__ void __launch_bounds__(128)
conv_bn_kernel(const float* __restrict__ in, const int* __restrict__ nbr,
               const float* __restrict__ Wt,
               const float* __restrict__ gamma, const float* __restrict__ beta,
               const float* __restrict__ mean, const float* __restrict__ var,
               const float* __restrict__ res, float* __restrict__ out, int n) {
    __shared__ float sW[9 * CIN * 32];
    __shared__ float sA[CIN * 64];

    const int t = threadIdx.x;
    const int base = blockIdx.x * 64;

    // stage full weight tensor into smem (vectorized)
    constexpr int W_F4 = 9 * CIN * 32 / 4;
#pragma unroll
    for (int idx = t; idx < W_F4; idx += 128)
        reinterpret_cast<float4*>(sW)[idx] =
            reinterpret_cast<const float4*>(Wt)[idx];

    // thread -> (point group, channel group)
    const int pg = t & 15;        // 16 point groups
    const int cg = t >> 4;        // 8 channel groups
    const int m0 = pg * 4;
    const int c0 = cg * 4;

    // fused BN coefficients for this thread's 4 channels
    float sc[4], sh[4];
#pragma unroll
    for (int j = 0; j < 4; ++j) {
        int c = c0 + j;
        float s = gamma[c] * rsqrtf(var[c] + BN_EPS);
        sc[j] = s;
        sh[j] = beta[c] - mean[c] * s;
    }

    // accumulators: 4 points x 2 channel-pairs (f32x2)
    unsigned long long acc[4][2];
#pragma unroll
    for (int p = 0; p < 4; ++p) { acc[p][0] = 0ull; acc[p][1] = 0ull; }

    // gather thread mapping: 2 threads per point, each loads CIN/2 channels
    const int gm = t & 63;        // point within tile
    const int gh = t >> 6;        // half (0/1)
    constexpr int F4H = CIN / 8;  // float4 loads per half

    for (int k = 0; k < 9; ++k) {
        __syncthreads();  // sA safe to overwrite (also covers sW on k==0)

        // ---- gather k-th neighbor features into sA[ci][m] ----
        int gi = base + gm;
        int ni = (gi < n) ? nbr[k * n + gi] : -1;
#pragma unroll
        for (int q = 0; q < F4H; ++q) {
            int c4 = gh * F4H + q;
            float4 v = make_float4(0.f, 0.f, 0.f, 0.f);
            if (ni >= 0)
                v = *reinterpret_cast<const float4*>(in + (size_t)ni * CIN + c4 * 4);
            sA[(c4 * 4 + 0) * 64 + gm] = v.x;
            sA[(c4 * 4 + 1) * 64 + gm] = v.y;
            sA[(c4 * 4 + 2) * 64 + gm] = v.z;
            sA[(c4 * 4 + 3) * 64 + gm] = v.w;
        }
        __syncthreads();

        // ---- GEMM slice: acc += A_k^T(ci over CIN) * W_k ----
        const float* sWk = sW + k * CIN * 32;
#pragma unroll
        for (int ci = 0; ci < CIN; ++ci) {
            float4 av = *reinterpret_cast<const float4*>(&sA[ci * 64 + m0]);
            float4 bv = *reinterpret_cast<const float4*>(&sWk[ci * 32 + c0]);
            unsigned long long b01, b23;
            asm("mov.b64 %0, {%1, %2};" : "=l"(b01) : "f"(bv.x), "f"(bv.y));
            asm("mov.b64 %0, {%1, %2};" : "=l"(b23) : "f"(bv.z), "f"(bv.w));
            float a_[4] = {av.x, av.y, av.z, av.w};
#pragma unroll
            for (int p = 0; p < 4; ++p) {
                unsigned long long ad;
                asm("mov.b64 %0, {%1, %1};" : "=l"(ad) : "f"(a_[p]));
                asm("fma.rn.f32x2 %0, %1, %2, %0;"
                    : "+l"(acc[p][0]) : "l"(ad), "l"(b01));
                asm("fma.rn.f32x2 %0, %1, %2, %0;"
                    : "+l"(acc[p][1]) : "l"(ad), "l"(b23));
            }
        }
    }

    // ---- epilogue: BN + LeakyReLU (+ residual), float4 stores ----
#pragma unroll
    for (int p = 0; p < 4; ++p) {
        int gi = base + m0 + p;
        if (gi >= n) break;
        float o0, o1, o2, o3;
        asm("mov.b64 {%0, %1}, %2;" : "=f"(o0), "=f"(o1) : "l"(acc[p][0]));
        asm("mov.b64 {%0, %1}, %2;" : "=f"(o2), "=f"(o3) : "l"(acc[p][1]));
        float y0 = o0 * sc[0] + sh[0];
        float y1 = o1 * sc[1] + sh[1];
        float y2 = o2 * sc[2] + sh[2];
        float y3 = o3 * sc[3] + sh[3];
        y0 = (y0 >= 0.f) ? y0 : NEG_SLOPE * y0;
        y1 = (y1 >= 0.f) ? y1 : NEG_SLOPE * y1;
        y2 = (y2 >= 0.f) ? y2 : NEG_SLOPE * y2;
        y3 = (y3 >= 0.f) ? y3 : NEG_SLOPE * y3;
        if (ADD) {
            float4 rv = *reinterpret_cast<const float4*>(res + (size_t)gi * 32 + c0);
            y0 += rv.x; y1 += rv.y; y2 += rv.z; y3 += rv.w;
        }
        float4 ov = make_float4(y0, y1, y2, y3);
        *reinterpret_cast<float4*>(out + (size_t)gi * 32 + c0) = ov;
    }
}

// ---------------------------------------------------------------------------
// Host launcher: graph-capturable (kernel launches only)
// Inputs: 0 feats(N,16) 1 coords(N,4) 2..5 W1..W4 6..9 gamma/beta/mean/var(4,32)
// ---------------------------------------------------------------------------
extern "C" void kernel_launch(void* const* d_in, const int* in_sizes, int n_in,
                              void* d_out, int out_size) {
    const float* feats  = (const float*)d_in[0];
    const int*   coords = (const int*)d_in[1];
    const float* W1     = (const float*)d_in[2];
    const float* W2     = (const float*)d_in[3];
    const float* W3     = (const float*)d_in[4];
    const float* W4     = (const float*)d_in[5];
    const float* gamma  = (const float*)d_in[6];
    const float* beta   = (const float*)d_in[7];
    const float* mean   = (const float*)d_in[8];
    const float* var    = (const float*)d_in[9];
    float* out = (float*)d_out;

    int n = in_sizes[1] / 4;  // coords is (N,4)

    void *p_n133, *p_n313, *p_b1, *p_b2;
    cudaGetSymbolAddress(&p_n133, g_nbr133);
    cudaGetSymbolAddress(&p_n313, g_nbr313);
    cudaGetSymbolAddress(&p_b1, g_buf1);
    cudaGetSymbolAddress(&p_b2, g_buf2);
    int*   n133 = (int*)p_n133;
    int*   n313 = (int*)p_n313;
    float* b1   = (float*)p_b1;
    float* b2   = (float*)p_b2;

    int blk = 256;
    int gscat = (n + blk - 1) / blk;
    scatter_grid_kernel<<<gscat, blk>>>(coords, n);
    build_nbrs_kernel<<<gscat, blk>>>(coords, n, n133, n313);

    int tiles = (n + 63) / 64;
    // conv1: feats -> b1   (W1, OFF_133, bn layer 0)
    conv_bn_kernel<16, false><<<tiles, 128>>>(feats, n133, W1,
        gamma + 0, beta + 0, mean + 0, var + 0, nullptr, b1, n);
    // conv2: b1 -> b2 (shortcut)   (W2, OFF_313, bn layer 1)
    conv_bn_kernel<32, false><<<tiles, 128>>>(b1, n313, W2,
        gamma + 32, beta + 32, mean + 32, var + 32, nullptr, b2, n);
    // conv3: feats -> b1   (W3, OFF_313, bn layer 2)
    conv_bn_kernel<16, false><<<tiles, 128>>>(feats, n313, W3,
        gamma + 64, beta + 64, mean + 64, var + 64, nullptr, b1, n);
    // conv4: b1 -> out (+ b2)   (W4, OFF_133, bn layer 3)
    conv_bn_kernel<32, true><<<tiles, 128>>>(b1, n133, W4,
        gamma + 96, beta + 96, mean + 96, var + 96, b2, out, n);
}

// round 7
// speedup vs baseline: 1.0043x; 1.0043x over previous
#include <cuda_runtime.h>
#include <cstdint>

// Problem constants (fixed by the dataset)
#define DD 480
#define HH 360
#define WWD 32
#define BB 2
#define NPTS_MAX 200000
#define NEG_SLOPE 0.01f
#define BN_EPS 1e-5f

static constexpr int GRID_SZ = BB * DD * HH * WWD;  // 11,059,200

// Scratch (device globals: allowed; zero-initialized at module load)
__device__ int   g_grid[GRID_SZ];          // stores idx+1; 0 == empty
__device__ int   g_nbr133[9 * NPTS_MAX];   // k-major: [k*n + i]
__device__ int   g_nbr313[9 * NPTS_MAX];
__device__ float g_buf1[NPTS_MAX * 32];
__device__ float g_buf2[NPTS_MAX * 32];

// ---------------------------------------------------------------------------
// Kernel 1: scatter point index into dense grid (idx+1; empty cells stay 0
// from static zero-init; same positions rewritten every call -> deterministic)
// ---------------------------------------------------------------------------
__global__ void scatter_grid_kernel(const int* __restrict__ coords, int n) {
    int i = blockIdx.x * blockDim.x + threadIdx.x;
    if (i >= n) return;
    int b = coords[i * 4 + 0];
    int z = coords[i * 4 + 1];
    int y = coords[i * 4 + 2];
    int x = coords[i * 4 + 3];
    int lin = ((b * DD + z) * HH + y) * WWD + x;
    g_grid[lin] = i + 1;
}

// ---------------------------------------------------------------------------
// Kernel 2: build both neighbor tables (OFF_133: dz=0; OFF_313: dy=0)
// ---------------------------------------------------------------------------
__global__ void build_nbrs_kernel(const int* __restrict__ coords, int n,
                                  int* __restrict__ nbr133,
                                  int* __restrict__ nbr313) {
    int i = blockIdx.x * blockDim.x + threadIdx.x;
    if (i >= n) return;
    int b = coords[i * 4 + 0];
    int z = coords[i * 4 + 1];
    int y = coords[i * 4 + 2];
    int x = coords[i * 4 + 3];
    int base_bz = (b * DD + z);
#pragma unroll
    for (int k = 0; k < 9; ++k) {
        int d0 = k / 3 - 1;
        int d1 = k % 3 - 1;
        {   // OFF_133: (0, dy, dx)
            int ny = y + d0, nx = x + d1;
            int r = -1;
            if (ny >= 0 && ny < HH && nx >= 0 && nx < WWD)
                r = g_grid[(base_bz * HH + ny) * WWD + nx] - 1;
            nbr133[k * n + i] = r;
        }
        {   // OFF_313: (dz, 0, dx)
            int nz = z + d0, nx = x + d1;
            int r = -1;
            if (nz >= 0 && nz < DD && nx >= 0 && nx < WWD)
                r = g_grid[((b * DD + nz) * HH + y) * WWD + nx] - 1;
            nbr313[k * n + i] = r;
        }
    }
}

// ---------------------------------------------------------------------------
// Kernel 3: fused gather-GEMM + BN + LeakyReLU (+ optional residual)
//
// Block: 256 points x 32 channels, 128 threads.
// Thread tile: 8 points x 8 channels. Points split into two groups of 4
// (ptg*4 and 128+ptg*4) so A-tile LDS.128s are lane-contiguous (0 conflicts).
// A is read as packed point-pairs (ld.shared.v2.b64) feeding fma.rn.f32x2
// directly; W is staged pre-duplicated ({w,w}) so B also loads packed.
// Inner loop per ci: 6 LDS.128 + 32 FFMA2 -> fma-pipe bound.
// ---------------------------------------------------------------------------
template <int CIN, bool ADD>
__global__ void __launch_bounds__(128)
conv_bn_kernel(const float* __restrict__ in, const int* __restrict__ nbr,
               const float* __restrict__ Wt,
               const float* __restrict__ gamma, const float* __restrict__ beta,
               const float* __restrict__ mean, const float* __restrict__ var,
               const float* __restrict__ res, float* __restrict__ out, int n) {
    __shared__ float  sA[CIN * 256];   // [ci][m]
    __shared__ float2 sWd[CIN * 32];   // duplicated W k-slice: [ci][c] = {w,w}

    const int t = threadIdx.x;
    const int base = blockIdx.x * 256;
    const int ptg = t & 31;   // 32 point groups
    const int chg = t >> 5;   // warp id -> channel group of 8
    const int c0 = chg * 8;

    // fused BN coefficients for this thread's 8 channels
    float sc[8], sh[8];
#pragma unroll
    for (int j = 0; j < 8; ++j) {
        int c = c0 + j;
        float s = gamma[c] * rsqrtf(var[c] + BN_EPS);
        sc[j] = s;
        sh[j] = beta[c] - mean[c] * s;
    }

    // accumulators: 4 point-pairs x 8 channels (f32x2: lo=even pt, hi=odd pt)
    unsigned long long acc[4][8];
#pragma unroll
    for (int p = 0; p < 4; ++p)
#pragma unroll
        for (int j = 0; j < 8; ++j) acc[p][j] = 0ull;

    const unsigned sA_sh  = (unsigned)__cvta_generic_to_shared(sA);
    const unsigned sWd_sh = (unsigned)__cvta_generic_to_shared(sWd);
    const unsigned aOff0 = sA_sh + ptg * 16;          // group 0: points ptg*4..+3
    const unsigned aOff1 = sA_sh + 512 + ptg * 16;    // group 1: points 128+ptg*4..+3
    const unsigned bOff  = sWd_sh + c0 * 8;

    const int* nbrk = nbr;
    for (int k = 0; k < 9; ++k, nbrk += n) {
        __syncthreads();  // sA/sWd safe to overwrite

        // ---- stage duplicated W k-slice ----
        const float* Wk = Wt + k * CIN * 32;
#pragma unroll
        for (int j = t; j < CIN * 32; j += 128) {
            float w = Wk[j];
            sWd[j] = make_float2(w, w);
        }

        // ---- gather k-th neighbor features into sA[ci][m] ----
#pragma unroll
        for (int half = 0; half < 2; ++half) {
            int m = half * 128 + t;
            int gi = base + m;
            int ni = (gi < n) ? nbrk[gi] : -1;
#pragma unroll
            for (int q = 0; q < CIN / 4; ++q) {
                float4 v = make_float4(0.f, 0.f, 0.f, 0.f);
                if (ni >= 0)
                    v = *reinterpret_cast<const float4*>(
                        in + (size_t)ni * CIN + q * 4);
                sA[(q * 4 + 0) * 256 + m] = v.x;
                sA[(q * 4 + 1) * 256 + m] = v.y;
                sA[(q * 4 + 2) * 256 + m] = v.z;
                sA[(q * 4 + 3) * 256 + m] = v.w;
            }
        }
        __syncthreads();

        // ---- GEMM slice: acc += A_k^T * W_k ----
#pragma unroll 8
        for (int ci = 0; ci < CIN; ++ci) {
            unsigned long long ap[4], bd[8];
            unsigned aRow = ci * 1024;   // 256 floats * 4B
            unsigned bRow = ci * 256;    // 32 pairs * 8B
            asm("ld.shared.v2.b64 {%0, %1}, [%2];"
                : "=l"(ap[0]), "=l"(ap[1]) : "r"(aOff0 + aRow));
            asm("ld.shared.v2.b64 {%0, %1}, [%2];"
                : "=l"(ap[2]), "=l"(ap[3]) : "r"(aOff1 + aRow));
            asm("ld.shared.v2.b64 {%0, %1}, [%2];"
                : "=l"(bd[0]), "=l"(bd[1]) : "r"(bOff + bRow));
            asm("ld.shared.v2.b64 {%0, %1}, [%2];"
                : "=l"(bd[2]), "=l"(bd[3]) : "r"(bOff + bRow + 16));
            asm("ld.shared.v2.b64 {%0, %1}, [%2];"
                : "=l"(bd[4]), "=l"(bd[5]) : "r"(bOff + bRow + 32));
            asm("ld.shared.v2.b64 {%0, %1}, [%2];"
                : "=l"(bd[6]), "=l"(bd[7]) : "r"(bOff + bRow + 48));
#pragma unroll
            for (int p = 0; p < 4; ++p)
#pragma unroll
                for (int j = 0; j < 8; ++j)
                    asm("fma.rn.f32x2 %0, %1, %2, %0;"
                        : "+l"(acc[p][j]) : "l"(ap[p]), "l"(bd[j]));
        }
    }

    // ---- epilogue: BN + LeakyReLU (+ residual) ----
    // acc[g*2+lp][j]: lo = point (g*128 + ptg*4 + lp*2), hi = that + 1
#pragma unroll
    for (int g = 0; g < 2; ++g) {
#pragma unroll
        for (int lp = 0; lp < 2; ++lp) {
            float ylo[8], yhi[8];
#pragma unroll
            for (int j = 0; j < 8; ++j)
                asm("mov.b64 {%0, %1}, %2;"
                    : "=f"(ylo[j]), "=f"(yhi[j]) : "l"(acc[g * 2 + lp][j]));
#pragma unroll
            for (int h = 0; h < 2; ++h) {
                int gi = base + g * 128 + ptg * 4 + lp * 2 + h;
                if (gi >= n) continue;
                const float* yy = h ? yhi : ylo;
                float y[8];
#pragma unroll
                for (int j = 0; j < 8; ++j) {
                    float v = yy[j] * sc[j] + sh[j];
                    y[j] = (v >= 0.f) ? v : NEG_SLOPE * v;
                }
                if (ADD) {
                    float4 r0 = *reinterpret_cast<const float4*>(
                        res + (size_t)gi * 32 + c0);
                    float4 r1 = *reinterpret_cast<const float4*>(
                        res + (size_t)gi * 32 + c0 + 4);
                    y[0] += r0.x; y[1] += r0.y; y[2] += r0.z; y[3] += r0.w;
                    y[4] += r1.x; y[5] += r1.y; y[6] += r1.z; y[7] += r1.w;
                }
                *reinterpret_cast<float4*>(out + (size_t)gi * 32 + c0) =
                    make_float4(y[0], y[1], y[2], y[3]);
                *reinterpret_cast<float4*>(out + (size_t)gi * 32 + c0 + 4) =
                    make_float4(y[4], y[5], y[6], y[7]);
            }
        }
    }
}

// ---------------------------------------------------------------------------
// Host launcher: graph-capturable (kernel launches only)
// Inputs: 0 feats(N,16) 1 coords(N,4) 2..5 W1..W4 6..9 gamma/beta/mean/var(4,32)
// ---------------------------------------------------------------------------
extern "C" void kernel_launch(void* const* d_in, const int* in_sizes, int n_in,
                              void* d_out, int out_size) {
    const float* feats  = (const float*)d_in[0];
    const int*   coords = (const int*)d_in[1];
    const float* W1     = (const float*)d_in[2];
    const float* W2     = (const float*)d_in[3];
    const float* W3     = (const float*)d_in[4];
    const float* W4     = (const float*)d_in[5];
    const float* gamma  = (const float*)d_in[6];
    const float* beta   = (const float*)d_in[7];
    const float* mean   = (const float*)d_in[8];
    const float* var    = (const float*)d_in[9];
    float* out = (float*)d_out;

    int n = in_sizes[1] / 4;  // coords is (N,4)

    void *p_n133, *p_n313, *p_b1, *p_b2;
    cudaGetSymbolAddress(&p_n133, g_nbr133);
    cudaGetSymbolAddress(&p_n313, g_nbr313);
    cudaGetSymbolAddress(&p_b1, g_buf1);
    cudaGetSymbolAddress(&p_b2, g_buf2);
    int*   n133 = (int*)p_n133;
    int*   n313 = (int*)p_n313;
    float* b1   = (float*)p_b1;
    float* b2   = (float*)p_b2;

    int blk = 256;
    int gscat = (n + blk - 1) / blk;
    scatter_grid_kernel<<<gscat, blk>>>(coords, n);
    build_nbrs_kernel<<<gscat, blk>>>(coords, n, n133, n313);

    int tiles = (n + 255) / 256;
    // conv1: feats -> b1   (W1, OFF_133, bn layer 0)
    conv_bn_kernel<16, false><<<tiles, 128>>>(feats, n133, W1,
        gamma + 0, beta + 0, mean + 0, var + 0, nullptr, b1, n);
    // conv2: b1 -> b2 (shortcut)   (W2, OFF_313, bn layer 1)
    conv_bn_kernel<32, false><<<tiles, 128>>>(b1, n313, W2,
        gamma + 32, beta + 32, mean + 32, var + 32, nullptr, b2, n);
    // conv3: feats -> b1   (W3, OFF_313, bn layer 2)
    conv_bn_kernel<16, false><<<tiles, 128>>>(feats, n313, W3,
        gamma + 64, beta + 64, mean + 64, var + 64, nullptr, b1, n);
    // conv4: b1 -> out (+ b2)   (W4, OFF_133, bn layer 3)
    conv_bn_kernel<32, true><<<tiles, 128>>>(b1, n133, W4,
        gamma + 96, beta + 96, mean + 96, var + 96, b2, out, n);
}